// round 4
// baseline (speedup 1.0000x reference)
#include <cuda_runtime.h>
#include <cuda_bf16.h>
#include <cstdint>
#include <cstddef>

#define BATCH   256
#define NTOK    197
#define EDIM    768
#define DDIM    64
#define SLOTS   10
#define HDIM    128
#define ODIM    768
#define MROWS   (BATCH * NTOK)
#define OUT_ELEMS (BATCH * SLOTS * ODIM)

// ---------------- device scratch ----------------
__device__ float          g_kv[(size_t)MROWS * 128];   // k: cols 0..63, v: cols 64..127
__device__ __nv_bfloat16  g_Wh[EDIM * 128];
__device__ __nv_bfloat16  g_Wl[EDIM * 128];
__device__ float          g_c1[128];
__device__ float          g_c2[128];
__device__ float          g_WihT[DDIM * 192];
__device__ float          g_WhhT[DDIM * 192];

// ---------------- mma helpers ----------------
__device__ __forceinline__ uint32_t smem_u32(const void* p) {
    return (uint32_t)__cvta_generic_to_shared(p);
}
__device__ __forceinline__ void ldsm_x4(uint32_t* d, const void* p) {
    uint32_t a = smem_u32(p);
    asm volatile("ldmatrix.sync.aligned.m8n8.x4.shared.b16 {%0,%1,%2,%3},[%4];"
                 : "=r"(d[0]), "=r"(d[1]), "=r"(d[2]), "=r"(d[3]) : "r"(a));
}
__device__ __forceinline__ void ldsm_x2t(uint32_t* d, const void* p) {
    uint32_t a = smem_u32(p);
    asm volatile("ldmatrix.sync.aligned.m8n8.x2.trans.shared.b16 {%0,%1},[%2];"
                 : "=r"(d[0]), "=r"(d[1]) : "r"(a));
}
__device__ __forceinline__ void mma16816(float* c, const uint32_t* a, const uint32_t* b) {
    asm volatile(
        "mma.sync.aligned.m16n8k16.row.col.f32.bf16.bf16.f32 "
        "{%0,%1,%2,%3},{%4,%5,%6,%7},{%8,%9},{%0,%1,%2,%3};"
        : "+f"(c[0]), "+f"(c[1]), "+f"(c[2]), "+f"(c[3])
        : "r"(a[0]), "r"(a[1]), "r"(a[2]), "r"(a[3]), "r"(b[0]), "r"(b[1]));
}

// ---------------- kernel 0: weight prep ----------------
__global__ void prep_kernel(const float* __restrict__ Wk, const float* __restrict__ Wv,
                            const float* __restrict__ g,  const float* __restrict__ bb,
                            const float* __restrict__ Wih, const float* __restrict__ Whh)
{
    int tid = blockIdx.x * blockDim.x + threadIdx.x;
    int nt  = gridDim.x * blockDim.x;
    for (int i = tid; i < EDIM * 128; i += nt) {
        int e = i >> 7, j = i & 127;
        float w  = (j < 64) ? Wk[e * 64 + j] : Wv[e * 64 + (j - 64)];
        float wp = g[e] * w;
        __nv_bfloat16 h = __float2bfloat16_rn(wp);
        g_Wh[i] = h;
        g_Wl[i] = __float2bfloat16_rn(wp - __bfloat162float(h));
    }
    for (int j = tid; j < 128; j += nt) {
        float a = 0.f, c = 0.f;
        for (int e = 0; e < EDIM; e++) {
            float w = (j < 64) ? Wk[e * 64 + j] : Wv[e * 64 + (j - 64)];
            a += g[e] * w;
            c += bb[e] * w;
        }
        g_c1[j] = a; g_c2[j] = c;
    }
    for (int i = tid; i < 192 * DDIM; i += nt) {
        int j = i / DDIM, d = i - j * DDIM;
        g_WihT[d * 192 + j] = Wih[i];
        g_WhhT[d * 192 + j] = Whh[i];
    }
}

// ---------------- kernel 1: fused LN + GEMM ----------------
struct SmemK1 {
    __nv_bfloat16 Ah[128][72];
    __nv_bfloat16 Al[128][72];
    __nv_bfloat16 Bh[64][136];
    __nv_bfloat16 Bl[64][136];
    float mean[128];
    float rstd[128];
};

__global__ void __launch_bounds__(256) k1_kernel(const float* __restrict__ f)
{
    extern __shared__ char smraw[];
    SmemK1& sm = *reinterpret_cast<SmemK1*>(smraw);
    const int t    = threadIdx.x;
    const int lane = t & 31;
    const int warp = t >> 5;
    const int wm   = warp >> 2;
    const int wn   = warp & 3;
    const int m0   = blockIdx.x * 128;

    float s1[8], s2[8];
#pragma unroll
    for (int i = 0; i < 8; i++) { s1[i] = 0.f; s2[i] = 0.f; }
    float acc[4][4][4];
#pragma unroll
    for (int a = 0; a < 4; a++)
#pragma unroll
        for (int b = 0; b < 4; b++)
#pragma unroll
            for (int c = 0; c < 4; c++) acc[a][b][c] = 0.f;

    const int arsub = t >> 4;
    const int acol  = (t & 15) * 4;
    const int bcol  = (t & 15) * 8;

    for (int kk = 0; kk < 12; kk++) {
        const int kb = kk * 64;
#pragma unroll
        for (int i = 0; i < 8; i++) {
            int r = i * 16 + arsub;
            const float4 xv = *reinterpret_cast<const float4*>(
                f + (size_t)(m0 + r) * EDIM + kb + acol);
            s1[i] += xv.x + xv.y + xv.z + xv.w;
            s2[i] += xv.x * xv.x + xv.y * xv.y + xv.z * xv.z + xv.w * xv.w;
            __nv_bfloat16 h0 = __float2bfloat16_rn(xv.x);
            __nv_bfloat16 h1 = __float2bfloat16_rn(xv.y);
            __nv_bfloat16 h2 = __float2bfloat16_rn(xv.z);
            __nv_bfloat16 h3 = __float2bfloat16_rn(xv.w);
            __nv_bfloat16 l0 = __float2bfloat16_rn(xv.x - __bfloat162float(h0));
            __nv_bfloat16 l1 = __float2bfloat16_rn(xv.y - __bfloat162float(h1));
            __nv_bfloat16 l2 = __float2bfloat16_rn(xv.z - __bfloat162float(h2));
            __nv_bfloat16 l3 = __float2bfloat16_rn(xv.w - __bfloat162float(h3));
            __nv_bfloat162* ph = reinterpret_cast<__nv_bfloat162*>(&sm.Ah[r][acol]);
            __nv_bfloat162* pl = reinterpret_cast<__nv_bfloat162*>(&sm.Al[r][acol]);
            __nv_bfloat162 u; u.x = h0; u.y = h1; ph[0] = u;
            u.x = h2; u.y = h3; ph[1] = u;
            u.x = l0; u.y = l1; pl[0] = u;
            u.x = l2; u.y = l3; pl[1] = u;
        }
#pragma unroll
        for (int i = 0; i < 4; i++) {
            int r = i * 16 + arsub;
            *reinterpret_cast<uint4*>(&sm.Bh[r][bcol]) =
                *reinterpret_cast<const uint4*>(&g_Wh[(kb + r) * 128 + bcol]);
            *reinterpret_cast<uint4*>(&sm.Bl[r][bcol]) =
                *reinterpret_cast<const uint4*>(&g_Wl[(kb + r) * 128 + bcol]);
        }
        __syncthreads();
#pragma unroll
        for (int ks = 0; ks < 4; ks++) {
            const int k0 = ks * 16;
            uint32_t bh[4][2], bl[4][2];
#pragma unroll
            for (int nt = 0; nt < 4; nt++) {
                const int n0 = wn * 32 + nt * 8;
                ldsm_x2t(bh[nt], &sm.Bh[k0 + (lane & 15)][n0]);
                ldsm_x2t(bl[nt], &sm.Bl[k0 + (lane & 15)][n0]);
            }
#pragma unroll
            for (int mt = 0; mt < 4; mt++) {
                uint32_t ah[4], al[4];
                const int ar = wm * 64 + mt * 16 + (lane & 15);
                const int ac = k0 + (lane >> 4) * 8;
                ldsm_x4(ah, &sm.Ah[ar][ac]);
                ldsm_x4(al, &sm.Al[ar][ac]);
#pragma unroll
                for (int nt = 0; nt < 4; nt++) {
                    mma16816(acc[mt][nt], ah, bh[nt]);
                    mma16816(acc[mt][nt], ah, bl[nt]);
                    mma16816(acc[mt][nt], al, bh[nt]);
                }
            }
        }
        __syncthreads();
    }

#pragma unroll
    for (int i = 0; i < 8; i++) {
        float a = s1[i], q = s2[i];
#pragma unroll
        for (int off = 8; off; off >>= 1) {
            a += __shfl_xor_sync(0xffffffffu, a, off);
            q += __shfl_xor_sync(0xffffffffu, q, off);
        }
        if ((t & 15) == 0) {
            int r = i * 16 + arsub;
            float mean = a * (1.0f / 768.0f);
            float var  = q * (1.0f / 768.0f) - mean * mean;
            sm.mean[r] = mean;
            sm.rstd[r] = rsqrtf(var + 1e-5f);
        }
    }
    __syncthreads();

#pragma unroll
    for (int mt = 0; mt < 4; mt++) {
#pragma unroll
        for (int nt = 0; nt < 4; nt++) {
            const int col = wn * 32 + nt * 8 + (lane & 3) * 2;
            const float c1a = g_c1[col],     c2a = g_c2[col];
            const float c1b = g_c1[col + 1], c2b = g_c2[col + 1];
#pragma unroll
            for (int hh = 0; hh < 2; hh++) {
                const int row = wm * 64 + mt * 16 + (lane >> 2) + hh * 8;
                const float rs = sm.rstd[row];
                const float base = -rs * sm.mean[row];
                float v0 = rs * acc[mt][nt][hh * 2 + 0] + base * c1a + c2a;
                float v1 = rs * acc[mt][nt][hh * 2 + 1] + base * c1b + c2b;
                *reinterpret_cast<float2*>(g_kv + (size_t)(m0 + row) * 128 + col)
                    = make_float2(v0, v1);
            }
        }
    }
}

// ---------------- kernel 2: slot attention + output ----------------
struct SmemK2 {
    float ksm[NTOK][65];
    float vts[DDIM][199];
    float attn[SLOTS][NTOK];
    float G1[SLOTS][192];
    float G2[SLOTS][192];
    float hbuf[SLOTS][HDIM];
    float slots[SLOTS][DDIM];
    float prev[SLOTS][DDIM];
    float qbuf[SLOTS][DDIM];
    float upd[SLOTS][DDIM];
    float lnb[SLOTS][DDIM];
    float rowinv[SLOTS];
};

__global__ void __launch_bounds__(256) k2_kernel(
    const float* __restrict__ slots_init,
    const float* __restrict__ ln_s_g, const float* __restrict__ ln_s_b,
    const float* __restrict__ Wq,
    const float* __restrict__ b_ih, const float* __restrict__ b_hh,
    const float* __restrict__ ln_m_g, const float* __restrict__ ln_m_b,
    const float* __restrict__ W1, const float* __restrict__ b1,
    const float* __restrict__ W2, const float* __restrict__ b2,
    const float* __restrict__ Wo, const float* __restrict__ bo,
    float* __restrict__ out)
{
    extern __shared__ char smraw[];
    SmemK2& sm = *reinterpret_cast<SmemK2*>(smraw);
    const int t    = threadIdx.x;
    const int lane = t & 31;
    const int warp = t >> 5;
    const int b    = blockIdx.x;
    const float* kvbase = g_kv + (size_t)b * NTOK * 128;

    for (int idx = t; idx < NTOK * DDIM; idx += 256) {
        int n = idx >> 6, d = idx & 63;
        sm.ksm[n][d] = kvbase[n * 128 + d];
        sm.vts[d][n] = kvbase[n * 128 + 64 + d];
    }
    for (int idx = t; idx < SLOTS * DDIM; idx += 256)
        sm.slots[idx >> 6][idx & 63] = slots_init[idx];
    __syncthreads();

    for (int it = 0; it < 3; it++) {
        for (int idx = t; idx < SLOTS * DDIM; idx += 256)
            sm.prev[idx >> 6][idx & 63] = sm.slots[idx >> 6][idx & 63];
        __syncthreads();
        for (int s = warp; s < SLOTS; s += 8) {
            float x0 = sm.slots[s][lane], x1 = sm.slots[s][lane + 32];
            float su = x0 + x1, sq = x0 * x0 + x1 * x1;
#pragma unroll
            for (int off = 16; off; off >>= 1) {
                su += __shfl_xor_sync(0xffffffffu, su, off);
                sq += __shfl_xor_sync(0xffffffffu, sq, off);
            }
            float mean = su * (1.f / 64.f);
            float rs   = rsqrtf(sq * (1.f / 64.f) - mean * mean + 1e-5f);
            sm.lnb[s][lane]      = (x0 - mean) * rs * __ldg(ln_s_g + lane)      + __ldg(ln_s_b + lane);
            sm.lnb[s][lane + 32] = (x1 - mean) * rs * __ldg(ln_s_g + lane + 32) + __ldg(ln_s_b + lane + 32);
        }
        __syncthreads();
        for (int idx = t; idx < SLOTS * DDIM; idx += 256) {
            int s = idx >> 6, d = idx & 63;
            float a = 0.f;
#pragma unroll 16
            for (int e = 0; e < 64; e++) a += sm.lnb[s][e] * __ldg(Wq + e * 64 + d);
            sm.qbuf[s][d] = a;
        }
        __syncthreads();
        for (int idx = t; idx < SLOTS * NTOK; idx += 256) {
            int s = idx / NTOK, n = idx - s * NTOK;
            float a = 0.f;
#pragma unroll 16
            for (int c = 0; c < 64; c++) a += sm.qbuf[s][c] * sm.ksm[n][c];
            sm.attn[s][n] = 0.125f * a;
        }
        __syncthreads();
        for (int n = t; n < NTOK; n += 256) {
            float mx = -1e30f;
#pragma unroll
            for (int s = 0; s < SLOTS; s++) mx = fmaxf(mx, sm.attn[s][n]);
            float e_[SLOTS]; float sum = 0.f;
#pragma unroll
            for (int s = 0; s < SLOTS; s++) { e_[s] = __expf(sm.attn[s][n] - mx); sum += e_[s]; }
            float inv = 1.f / sum;
#pragma unroll
            for (int s = 0; s < SLOTS; s++) sm.attn[s][n] = e_[s] * inv + 1e-8f;
        }
        __syncthreads();
        for (int s = warp; s < SLOTS; s += 8) {
            float a = 0.f;
            for (int n = lane; n < NTOK; n += 32) a += sm.attn[s][n];
#pragma unroll
            for (int off = 16; off; off >>= 1) a += __shfl_xor_sync(0xffffffffu, a, off);
            if (lane == 0) sm.rowinv[s] = 1.f / a;
        }
        __syncthreads();
        for (int idx = t; idx < SLOTS * DDIM; idx += 256) {
            int s = idx >> 6, d = idx & 63;
            float a = 0.f;
            for (int n = 0; n < NTOK; n++) a += sm.attn[s][n] * sm.vts[d][n];
            sm.upd[s][d] = a * sm.rowinv[s];
        }
        __syncthreads();
        for (int idx = t; idx < SLOTS * 192; idx += 256) {
            int s = idx / 192, j = idx - s * 192;
            float a = __ldg(b_ih + j), c = __ldg(b_hh + j);
#pragma unroll 16
            for (int d = 0; d < 64; d++) {
                a += sm.upd[s][d]  * g_WihT[d * 192 + j];
                c += sm.prev[s][d] * g_WhhT[d * 192 + j];
            }
            sm.G1[s][j] = a; sm.G2[s][j] = c;
        }
        __syncthreads();
        for (int idx = t; idx < SLOTS * DDIM; idx += 256) {
            int s = idx >> 6, d = idx & 63;
            float r  = 1.f / (1.f + __expf(-(sm.G1[s][d]      + sm.G2[s][d])));
            float z  = 1.f / (1.f + __expf(-(sm.G1[s][64 + d] + sm.G2[s][64 + d])));
            float nn = tanhf(sm.G1[s][128 + d] + r * sm.G2[s][128 + d]);
            sm.slots[s][d] = (1.f - z) * nn + z * sm.prev[s][d];
        }
        __syncthreads();
        for (int s = warp; s < SLOTS; s += 8) {
            float x0 = sm.slots[s][lane], x1 = sm.slots[s][lane + 32];
            float su = x0 + x1, sq = x0 * x0 + x1 * x1;
#pragma unroll
            for (int off = 16; off; off >>= 1) {
                su += __shfl_xor_sync(0xffffffffu, su, off);
                sq += __shfl_xor_sync(0xffffffffu, sq, off);
            }
            float mean = su * (1.f / 64.f);
            float rs   = rsqrtf(sq * (1.f / 64.f) - mean * mean + 1e-5f);
            sm.lnb[s][lane]      = (x0 - mean) * rs * __ldg(ln_m_g + lane)      + __ldg(ln_m_b + lane);
            sm.lnb[s][lane + 32] = (x1 - mean) * rs * __ldg(ln_m_g + lane + 32) + __ldg(ln_m_b + lane + 32);
        }
        __syncthreads();
        for (int idx = t; idx < SLOTS * HDIM; idx += 256) {
            int s = idx >> 7, i = idx & 127;
            float a = __ldg(b1 + i);
#pragma unroll 16
            for (int d = 0; d < 64; d++) a += sm.lnb[s][d] * __ldg(W1 + d * 128 + i);
            sm.hbuf[s][i] = fmaxf(a, 0.f);
        }
        __syncthreads();
        for (int idx = t; idx < SLOTS * DDIM; idx += 256) {
            int s = idx >> 6, d = idx & 63;
            float a = __ldg(b2 + d);
#pragma unroll 16
            for (int i = 0; i < 128; i++) a += sm.hbuf[s][i] * __ldg(W2 + i * 64 + d);
            sm.slots[s][d] += a;
        }
        __syncthreads();
    }

    float* out2 = out + OUT_ELEMS;
    for (int idx = t; idx < SLOTS * DDIM; idx += 256)
        out2[(size_t)b * SLOTS * DDIM + idx] = sm.slots[idx >> 6][idx & 63];

    for (int o = t; o < ODIM; o += 256) {
        float a[SLOTS];
        const float bov = __ldg(bo + o);
#pragma unroll
        for (int s = 0; s < SLOTS; s++) a[s] = bov;
        for (int d = 0; d < 64; d++) {
            const float w = __ldg(Wo + d * ODIM + o);
            const float* sl = &sm.slots[0][0];
#pragma unroll
            for (int s = 0; s < SLOTS; s++) a[s] += sl[s * DDIM + d] * w;
        }
#pragma unroll
        for (int s = 0; s < SLOTS; s++)
            out[((size_t)(b * SLOTS + s)) * ODIM + o] = fmaxf(a[s], 0.f);
    }
}

// ---------------- launch ----------------
extern "C" void kernel_launch(void* const* d_in, const int* in_sizes, int n_in,
                              void* d_out, int out_size)
{
    const float* features   = (const float*)d_in[0];
    const float* ln_in_g    = (const float*)d_in[1];
    const float* ln_in_b    = (const float*)d_in[2];
    const float* slots_init = (const float*)d_in[3];
    const float* ln_s_g     = (const float*)d_in[4];
    const float* ln_s_b     = (const float*)d_in[5];
    const float* Wq         = (const float*)d_in[6];
    const float* Wk         = (const float*)d_in[7];
    const float* Wv         = (const float*)d_in[8];
    const float* W_ih       = (const float*)d_in[9];
    const float* W_hh       = (const float*)d_in[10];
    const float* b_ih       = (const float*)d_in[11];
    const float* b_hh       = (const float*)d_in[12];
    const float* ln_m_g     = (const float*)d_in[13];
    const float* ln_m_b     = (const float*)d_in[14];
    const float* W1         = (const float*)d_in[15];
    const float* b1         = (const float*)d_in[16];
    const float* W2         = (const float*)d_in[17];
    const float* b2         = (const float*)d_in[18];
    const float* Wo         = (const float*)d_in[19];
    const float* bo         = (const float*)d_in[20];
    float* out = (float*)d_out;

    cudaFuncSetAttribute(k1_kernel, cudaFuncAttributeMaxDynamicSharedMemorySize,
                         (int)sizeof(SmemK1));
    cudaFuncSetAttribute(k2_kernel, cudaFuncAttributeMaxDynamicSharedMemorySize,
                         (int)sizeof(SmemK2));

    prep_kernel<<<8, 256>>>(Wk, Wv, ln_in_g, ln_in_b, W_ih, W_hh);
    k1_kernel<<<MROWS / 128, 256, sizeof(SmemK1)>>>(features);
    k2_kernel<<<BATCH, 256, sizeof(SmemK2)>>>(slots_init, ln_s_g, ln_s_b, Wq,
                                              b_ih, b_hh, ln_m_g, ln_m_b,
                                              W1, b1, W2, b2, Wo, bo, out);
}

// round 6
// speedup vs baseline: 1.4643x; 1.4643x over previous
#include <cuda_runtime.h>
#include <cuda_bf16.h>
#include <cstdint>
#include <cstddef>

#define BATCH   256
#define NTOK    197
#define EDIM    768
#define DDIM    64
#define SLOTS   10
#define HDIM    128
#define ODIM    768
#define MROWS   (BATCH * NTOK)
#define OUT_ELEMS (BATCH * SLOTS * ODIM)
#define K2_THREADS 512
#define K2_WARPS   16

// ---------------- device scratch ----------------
__device__ float          g_kv[(size_t)MROWS * 128];   // k: cols 0..63, v: cols 64..127
__device__ __nv_bfloat16  g_Wh[EDIM * 128];
__device__ __nv_bfloat16  g_Wl[EDIM * 128];
__device__ float          g_c1[128];
__device__ float          g_c2[128];
__device__ float          g_WihT[DDIM * 192];
__device__ float          g_WhhT[DDIM * 192];

// ---------------- mma helpers ----------------
__device__ __forceinline__ uint32_t smem_u32(const void* p) {
    return (uint32_t)__cvta_generic_to_shared(p);
}
__device__ __forceinline__ void ldsm_x4(uint32_t* d, const void* p) {
    uint32_t a = smem_u32(p);
    asm volatile("ldmatrix.sync.aligned.m8n8.x4.shared.b16 {%0,%1,%2,%3},[%4];"
                 : "=r"(d[0]), "=r"(d[1]), "=r"(d[2]), "=r"(d[3]) : "r"(a));
}
__device__ __forceinline__ void ldsm_x2t(uint32_t* d, const void* p) {
    uint32_t a = smem_u32(p);
    asm volatile("ldmatrix.sync.aligned.m8n8.x2.trans.shared.b16 {%0,%1},[%2];"
                 : "=r"(d[0]), "=r"(d[1]) : "r"(a));
}
__device__ __forceinline__ void mma16816(float* c, const uint32_t* a, const uint32_t* b) {
    asm volatile(
        "mma.sync.aligned.m16n8k16.row.col.f32.bf16.bf16.f32 "
        "{%0,%1,%2,%3},{%4,%5,%6,%7},{%8,%9},{%0,%1,%2,%3};"
        : "+f"(c[0]), "+f"(c[1]), "+f"(c[2]), "+f"(c[3])
        : "r"(a[0]), "r"(a[1]), "r"(a[2]), "r"(a[3]), "r"(b[0]), "r"(b[1]));
}

// ---------------- kernel 0: weight prep (parallelized) ----------------
__global__ void __launch_bounds__(256) prep_kernel(
    const float* __restrict__ Wk, const float* __restrict__ Wv,
    const float* __restrict__ g,  const float* __restrict__ bb,
    const float* __restrict__ Wih, const float* __restrict__ Whh)
{
    const int tid = blockIdx.x * blockDim.x + threadIdx.x;
    const int nt  = gridDim.x * blockDim.x;
    const int lane = threadIdx.x & 31;
    const int gwarp = tid >> 5;

    for (int i = tid; i < EDIM * 128; i += nt) {
        int e = i >> 7, j = i & 127;
        float w  = (j < 64) ? Wk[e * 64 + j] : Wv[e * 64 + (j - 64)];
        float wp = g[e] * w;
        __nv_bfloat16 h = __float2bfloat16_rn(wp);
        g_Wh[i] = h;
        g_Wl[i] = __float2bfloat16_rn(wp - __bfloat162float(h));
    }

    if (gwarp < 128) {
        const int j = gwarp;
        float a = 0.f, c = 0.f;
        for (int e = lane; e < EDIM; e += 32) {
            float w = (j < 64) ? Wk[e * 64 + j] : Wv[e * 64 + (j - 64)];
            a += g[e] * w;
            c += bb[e] * w;
        }
#pragma unroll
        for (int off = 16; off; off >>= 1) {
            a += __shfl_xor_sync(0xffffffffu, a, off);
            c += __shfl_xor_sync(0xffffffffu, c, off);
        }
        if (lane == 0) { g_c1[j] = a; g_c2[j] = c; }
    }

    for (int i = tid; i < 192 * DDIM; i += nt) {
        int j = i / DDIM, d = i - j * DDIM;
        g_WihT[d * 192 + j] = Wih[i];
        g_WhhT[d * 192 + j] = Whh[i];
    }
}

// ---------------- kernel 1: fused LN + GEMM ----------------
struct SmemK1 {
    __nv_bfloat16 Ah[128][72];
    __nv_bfloat16 Al[128][72];
    __nv_bfloat16 Bh[64][136];
    __nv_bfloat16 Bl[64][136];
    float mean[128];
    float rstd[128];
};

__global__ void __launch_bounds__(256, 2) k1_kernel(const float* __restrict__ f)
{
    extern __shared__ char smraw[];
    SmemK1& sm = *reinterpret_cast<SmemK1*>(smraw);
    const int t    = threadIdx.x;
    const int lane = t & 31;
    const int warp = t >> 5;
    const int wm   = warp >> 2;
    const int wn   = warp & 3;
    const int m0   = blockIdx.x * 128;

    float s1[8], s2[8];
#pragma unroll
    for (int i = 0; i < 8; i++) { s1[i] = 0.f; s2[i] = 0.f; }
    float acc[4][4][4];
#pragma unroll
    for (int a = 0; a < 4; a++)
#pragma unroll
        for (int b = 0; b < 4; b++)
#pragma unroll
            for (int c = 0; c < 4; c++) acc[a][b][c] = 0.f;

    const int arsub = t >> 4;
    const int acol  = (t & 15) * 4;
    const int bcol  = (t & 15) * 8;

    for (int kk = 0; kk < 12; kk++) {
        const int kb = kk * 64;
#pragma unroll
        for (int i = 0; i < 8; i++) {
            int r = i * 16 + arsub;
            const float4 xv = *reinterpret_cast<const float4*>(
                f + (size_t)(m0 + r) * EDIM + kb + acol);
            s1[i] += xv.x + xv.y + xv.z + xv.w;
            s2[i] += xv.x * xv.x + xv.y * xv.y + xv.z * xv.z + xv.w * xv.w;
            __nv_bfloat16 h0 = __float2bfloat16_rn(xv.x);
            __nv_bfloat16 h1 = __float2bfloat16_rn(xv.y);
            __nv_bfloat16 h2 = __float2bfloat16_rn(xv.z);
            __nv_bfloat16 h3 = __float2bfloat16_rn(xv.w);
            __nv_bfloat16 l0 = __float2bfloat16_rn(xv.x - __bfloat162float(h0));
            __nv_bfloat16 l1 = __float2bfloat16_rn(xv.y - __bfloat162float(h1));
            __nv_bfloat16 l2 = __float2bfloat16_rn(xv.z - __bfloat162float(h2));
            __nv_bfloat16 l3 = __float2bfloat16_rn(xv.w - __bfloat162float(h3));
            __nv_bfloat162* ph = reinterpret_cast<__nv_bfloat162*>(&sm.Ah[r][acol]);
            __nv_bfloat162* pl = reinterpret_cast<__nv_bfloat162*>(&sm.Al[r][acol]);
            __nv_bfloat162 u; u.x = h0; u.y = h1; ph[0] = u;
            u.x = h2; u.y = h3; ph[1] = u;
            u.x = l0; u.y = l1; pl[0] = u;
            u.x = l2; u.y = l3; pl[1] = u;
        }
#pragma unroll
        for (int i = 0; i < 4; i++) {
            int r = i * 16 + arsub;
            *reinterpret_cast<uint4*>(&sm.Bh[r][bcol]) =
                *reinterpret_cast<const uint4*>(&g_Wh[(kb + r) * 128 + bcol]);
            *reinterpret_cast<uint4*>(&sm.Bl[r][bcol]) =
                *reinterpret_cast<const uint4*>(&g_Wl[(kb + r) * 128 + bcol]);
        }
        __syncthreads();
#pragma unroll
        for (int ks = 0; ks < 4; ks++) {
            const int k0 = ks * 16;
            uint32_t bh[4][2], bl[4][2];
#pragma unroll
            for (int nt = 0; nt < 4; nt++) {
                const int n0 = wn * 32 + nt * 8;
                ldsm_x2t(bh[nt], &sm.Bh[k0 + (lane & 15)][n0]);
                ldsm_x2t(bl[nt], &sm.Bl[k0 + (lane & 15)][n0]);
            }
#pragma unroll
            for (int mt = 0; mt < 4; mt++) {
                uint32_t ah[4], al[4];
                const int ar = wm * 64 + mt * 16 + (lane & 15);
                const int ac = k0 + (lane >> 4) * 8;
                ldsm_x4(ah, &sm.Ah[ar][ac]);
                ldsm_x4(al, &sm.Al[ar][ac]);
#pragma unroll
                for (int nt = 0; nt < 4; nt++) {
                    mma16816(acc[mt][nt], ah, bh[nt]);
                    mma16816(acc[mt][nt], ah, bl[nt]);
                    mma16816(acc[mt][nt], al, bh[nt]);
                }
            }
        }
        __syncthreads();
    }

#pragma unroll
    for (int i = 0; i < 8; i++) {
        float a = s1[i], q = s2[i];
#pragma unroll
        for (int off = 8; off; off >>= 1) {
            a += __shfl_xor_sync(0xffffffffu, a, off);
            q += __shfl_xor_sync(0xffffffffu, q, off);
        }
        if ((t & 15) == 0) {
            int r = i * 16 + arsub;
            float mean = a * (1.0f / 768.0f);
            float var  = q * (1.0f / 768.0f) - mean * mean;
            sm.mean[r] = mean;
            sm.rstd[r] = rsqrtf(var + 1e-5f);
        }
    }
    __syncthreads();

#pragma unroll
    for (int mt = 0; mt < 4; mt++) {
#pragma unroll
        for (int nt = 0; nt < 4; nt++) {
            const int col = wn * 32 + nt * 8 + (lane & 3) * 2;
            const float c1a = g_c1[col],     c2a = g_c2[col];
            const float c1b = g_c1[col + 1], c2b = g_c2[col + 1];
#pragma unroll
            for (int hh = 0; hh < 2; hh++) {
                const int row = wm * 64 + mt * 16 + (lane >> 2) + hh * 8;
                const float rs = sm.rstd[row];
                const float base = -rs * sm.mean[row];
                float v0 = rs * acc[mt][nt][hh * 2 + 0] + base * c1a + c2a;
                float v1 = rs * acc[mt][nt][hh * 2 + 1] + base * c1b + c2b;
                *reinterpret_cast<float2*>(g_kv + (size_t)(m0 + row) * 128 + col)
                    = make_float2(v0, v1);
            }
        }
    }
}

// ---------------- kernel 2: slot attention + output ----------------
struct SmemK2 {
    float ksm[NTOK][65];
    float vts[DDIM][199];
    float attn[SLOTS][NTOK];
    float G1[SLOTS][192];
    float G2[SLOTS][192];
    float hbuf[SLOTS][HDIM];
    float slots[SLOTS][DDIM];
    float prev[SLOTS][DDIM];
    float qbuf[SLOTS][DDIM];
    float upd[SLOTS][DDIM];
    float lnb[SLOTS][DDIM];
    float rowinv[SLOTS];
};

__global__ void __launch_bounds__(K2_THREADS) k2_kernel(
    const float* __restrict__ slots_init,
    const float* __restrict__ ln_s_g, const float* __restrict__ ln_s_b,
    const float* __restrict__ Wq,
    const float* __restrict__ b_ih, const float* __restrict__ b_hh,
    const float* __restrict__ ln_m_g, const float* __restrict__ ln_m_b,
    const float* __restrict__ W1, const float* __restrict__ b1,
    const float* __restrict__ W2, const float* __restrict__ b2,
    const float* __restrict__ Wo, const float* __restrict__ bo,
    float* __restrict__ out)
{
    extern __shared__ char smraw[];
    SmemK2& sm = *reinterpret_cast<SmemK2*>(smraw);
    const int t    = threadIdx.x;
    const int lane = t & 31;
    const int warp = t >> 5;
    const int b    = blockIdx.x;
    const float* kvbase = g_kv + (size_t)b * NTOK * 128;

    for (int idx = t; idx < NTOK * DDIM; idx += K2_THREADS) {
        int n = idx >> 6, d = idx & 63;
        sm.ksm[n][d] = kvbase[n * 128 + d];
        sm.vts[d][n] = kvbase[n * 128 + 64 + d];
    }
    for (int idx = t; idx < SLOTS * DDIM; idx += K2_THREADS)
        sm.slots[idx >> 6][idx & 63] = slots_init[idx];
    __syncthreads();

    for (int it = 0; it < 3; it++) {
        for (int idx = t; idx < SLOTS * DDIM; idx += K2_THREADS)
            sm.prev[idx >> 6][idx & 63] = sm.slots[idx >> 6][idx & 63];
        __syncthreads();
        for (int s = warp; s < SLOTS; s += K2_WARPS) {
            float x0 = sm.slots[s][lane], x1 = sm.slots[s][lane + 32];
            float su = x0 + x1, sq = x0 * x0 + x1 * x1;
#pragma unroll
            for (int off = 16; off; off >>= 1) {
                su += __shfl_xor_sync(0xffffffffu, su, off);
                sq += __shfl_xor_sync(0xffffffffu, sq, off);
            }
            float mean = su * (1.f / 64.f);
            float rs   = rsqrtf(sq * (1.f / 64.f) - mean * mean + 1e-5f);
            sm.lnb[s][lane]      = (x0 - mean) * rs * __ldg(ln_s_g + lane)      + __ldg(ln_s_b + lane);
            sm.lnb[s][lane + 32] = (x1 - mean) * rs * __ldg(ln_s_g + lane + 32) + __ldg(ln_s_b + lane + 32);
        }
        __syncthreads();
        for (int idx = t; idx < SLOTS * DDIM; idx += K2_THREADS) {
            int s = idx >> 6, d = idx & 63;
            float a = 0.f;
#pragma unroll 16
            for (int e = 0; e < 64; e++) a += sm.lnb[s][e] * __ldg(Wq + e * 64 + d);
            sm.qbuf[s][d] = a;
        }
        __syncthreads();
        for (int idx = t; idx < SLOTS * NTOK; idx += K2_THREADS) {
            int s = idx / NTOK, n = idx - s * NTOK;
            float a = 0.f;
#pragma unroll 16
            for (int c = 0; c < 64; c++) a += sm.qbuf[s][c] * sm.ksm[n][c];
            sm.attn[s][n] = 0.125f * a;
        }
        __syncthreads();
        for (int n = t; n < NTOK; n += K2_THREADS) {
            float mx = -1e30f;
#pragma unroll
            for (int s = 0; s < SLOTS; s++) mx = fmaxf(mx, sm.attn[s][n]);
            float e_[SLOTS]; float sum = 0.f;
#pragma unroll
            for (int s = 0; s < SLOTS; s++) { e_[s] = __expf(sm.attn[s][n] - mx); sum += e_[s]; }
            float inv = 1.f / sum;
#pragma unroll
            for (int s = 0; s < SLOTS; s++) sm.attn[s][n] = e_[s] * inv + 1e-8f;
        }
        __syncthreads();
        for (int s = warp; s < SLOTS; s += K2_WARPS) {
            float a = 0.f;
            for (int n = lane; n < NTOK; n += 32) a += sm.attn[s][n];
#pragma unroll
            for (int off = 16; off; off >>= 1) a += __shfl_xor_sync(0xffffffffu, a, off);
            if (lane == 0) sm.rowinv[s] = 1.f / a;
        }
        __syncthreads();
        for (int idx = t; idx < SLOTS * DDIM; idx += K2_THREADS) {
            int s = idx >> 6, d = idx & 63;
            float a = 0.f;
            for (int n = 0; n < NTOK; n++) a += sm.attn[s][n] * sm.vts[d][n];
            sm.upd[s][d] = a * sm.rowinv[s];
        }
        __syncthreads();
        for (int idx = t; idx < SLOTS * 192; idx += K2_THREADS) {
            int s = idx / 192, j = idx - s * 192;
            float a = __ldg(b_ih + j), c = __ldg(b_hh + j);
#pragma unroll 16
            for (int d = 0; d < 64; d++) {
                a += sm.upd[s][d]  * g_WihT[d * 192 + j];
                c += sm.prev[s][d] * g_WhhT[d * 192 + j];
            }
            sm.G1[s][j] = a; sm.G2[s][j] = c;
        }
        __syncthreads();
        for (int idx = t; idx < SLOTS * DDIM; idx += K2_THREADS) {
            int s = idx >> 6, d = idx & 63;
            float r  = 1.f / (1.f + __expf(-(sm.G1[s][d]      + sm.G2[s][d])));
            float z  = 1.f / (1.f + __expf(-(sm.G1[s][64 + d] + sm.G2[s][64 + d])));
            float nn = tanhf(sm.G1[s][128 + d] + r * sm.G2[s][128 + d]);
            sm.slots[s][d] = (1.f - z) * nn + z * sm.prev[s][d];
        }
        __syncthreads();
        for (int s = warp; s < SLOTS; s += K2_WARPS) {
            float x0 = sm.slots[s][lane], x1 = sm.slots[s][lane + 32];
            float su = x0 + x1, sq = x0 * x0 + x1 * x1;
#pragma unroll
            for (int off = 16; off; off >>= 1) {
                su += __shfl_xor_sync(0xffffffffu, su, off);
                sq += __shfl_xor_sync(0xffffffffu, sq, off);
            }
            float mean = su * (1.f / 64.f);
            float rs   = rsqrtf(sq * (1.f / 64.f) - mean * mean + 1e-5f);
            sm.lnb[s][lane]      = (x0 - mean) * rs * __ldg(ln_m_g + lane)      + __ldg(ln_m_b + lane);
            sm.lnb[s][lane + 32] = (x1 - mean) * rs * __ldg(ln_m_g + lane + 32) + __ldg(ln_m_b + lane + 32);
        }
        __syncthreads();
        for (int idx = t; idx < SLOTS * HDIM; idx += K2_THREADS) {
            int s = idx >> 7, i = idx & 127;
            float a = __ldg(b1 + i);
#pragma unroll 16
            for (int d = 0; d < 64; d++) a += sm.lnb[s][d] * __ldg(W1 + d * 128 + i);
            sm.hbuf[s][i] = fmaxf(a, 0.f);
        }
        __syncthreads();
        for (int idx = t; idx < SLOTS * DDIM; idx += K2_THREADS) {
            int s = idx >> 6, d = idx & 63;
            float a = __ldg(b2 + d);
#pragma unroll 16
            for (int i = 0; i < 128; i++) a += sm.hbuf[s][i] * __ldg(W2 + i * 64 + d);
            sm.slots[s][d] += a;
        }
        __syncthreads();
    }

    float* out2 = out + OUT_ELEMS;
    for (int idx = t; idx < SLOTS * DDIM; idx += K2_THREADS)
        out2[(size_t)b * SLOTS * DDIM + idx] = sm.slots[idx >> 6][idx & 63];

    for (int o = t; o < ODIM; o += K2_THREADS) {
        float a[SLOTS];
        const float bov = __ldg(bo + o);
#pragma unroll
        for (int s = 0; s < SLOTS; s++) a[s] = bov;
        for (int d = 0; d < 64; d++) {
            const float w = __ldg(Wo + d * ODIM + o);
            const float* sl = &sm.slots[0][0];
#pragma unroll
            for (int s = 0; s < SLOTS; s++) a[s] += sl[s * DDIM + d] * w;
        }
#pragma unroll
        for (int s = 0; s < SLOTS; s++)
            out[((size_t)(b * SLOTS + s)) * ODIM + o] = fmaxf(a[s], 0.f);
    }
}

// ---------------- launch ----------------
extern "C" void kernel_launch(void* const* d_in, const int* in_sizes, int n_in,
                              void* d_out, int out_size)
{
    const float* features   = (const float*)d_in[0];
    const float* ln_in_g    = (const float*)d_in[1];
    const float* ln_in_b    = (const float*)d_in[2];
    const float* slots_init = (const float*)d_in[3];
    const float* ln_s_g     = (const float*)d_in[4];
    const float* ln_s_b     = (const float*)d_in[5];
    const float* Wq         = (const float*)d_in[6];
    const float* Wk         = (const float*)d_in[7];
    const float* Wv         = (const float*)d_in[8];
    const float* W_ih       = (const float*)d_in[9];
    const float* W_hh       = (const float*)d_in[10];
    const float* b_ih       = (const float*)d_in[11];
    const float* b_hh       = (const float*)d_in[12];
    const float* ln_m_g     = (const float*)d_in[13];
    const float* ln_m_b     = (const float*)d_in[14];
    const float* W1         = (const float*)d_in[15];
    const float* b1         = (const float*)d_in[16];
    const float* W2         = (const float*)d_in[17];
    const float* b2         = (const float*)d_in[18];
    const float* Wo         = (const float*)d_in[19];
    const float* bo         = (const float*)d_in[20];
    float* out = (float*)d_out;

    cudaFuncSetAttribute(k1_kernel, cudaFuncAttributeMaxDynamicSharedMemorySize,
                         (int)sizeof(SmemK1));
    cudaFuncSetAttribute(k2_kernel, cudaFuncAttributeMaxDynamicSharedMemorySize,
                         (int)sizeof(SmemK2));

    prep_kernel<<<256, 256>>>(Wk, Wv, ln_in_g, ln_in_b, W_ih, W_hh);
    k1_kernel<<<MROWS / 128, 256, sizeof(SmemK1)>>>(features);
    k2_kernel<<<BATCH, K2_THREADS, sizeof(SmemK2)>>>(slots_init, ln_s_g, ln_s_b, Wq,
                                                     b_ih, b_hh, ln_m_g, ln_m_b,
                                                     W1, b1, W2, b2, Wo, bo, out);
}

// round 7
// speedup vs baseline: 1.7373x; 1.1865x over previous
#include <cuda_runtime.h>
#include <cuda_bf16.h>
#include <cstdint>
#include <cstddef>

#define BATCH   256
#define NTOK    197
#define EDIM    768
#define DDIM    64
#define SLOTS   10
#define HDIM    128
#define ODIM    768
#define MROWS   (BATCH * NTOK)
#define OUT_ELEMS (BATCH * SLOTS * ODIM)
#define K2_THREADS 512
#define K2_WARPS   16

// ---------------- device scratch ----------------
__device__ float          g_kv[(size_t)MROWS * 128];   // k: cols 0..63, v: cols 64..127
__device__ __nv_bfloat16  g_Wh[EDIM * 128];
__device__ __nv_bfloat16  g_Wl[EDIM * 128];
__device__ float          g_c1[128];
__device__ float          g_c2[128];
__device__ float          g_WihT[DDIM * 192];
__device__ float          g_WhhT[DDIM * 192];

// ---------------- helpers ----------------
__device__ __forceinline__ uint32_t smem_u32(const void* p) {
    return (uint32_t)__cvta_generic_to_shared(p);
}
__device__ __forceinline__ void ldsm_x4(uint32_t* d, const void* p) {
    uint32_t a = smem_u32(p);
    asm volatile("ldmatrix.sync.aligned.m8n8.x4.shared.b16 {%0,%1,%2,%3},[%4];"
                 : "=r"(d[0]), "=r"(d[1]), "=r"(d[2]), "=r"(d[3]) : "r"(a));
}
__device__ __forceinline__ void ldsm_x2t(uint32_t* d, const void* p) {
    uint32_t a = smem_u32(p);
    asm volatile("ldmatrix.sync.aligned.m8n8.x2.trans.shared.b16 {%0,%1},[%2];"
                 : "=r"(d[0]), "=r"(d[1]) : "r"(a));
}
__device__ __forceinline__ void mma16816(float* c, const uint32_t* a, const uint32_t* b) {
    asm volatile(
        "mma.sync.aligned.m16n8k16.row.col.f32.bf16.bf16.f32 "
        "{%0,%1,%2,%3},{%4,%5,%6,%7},{%8,%9},{%0,%1,%2,%3};"
        : "+f"(c[0]), "+f"(c[1]), "+f"(c[2]), "+f"(c[3])
        : "r"(a[0]), "r"(a[1]), "r"(a[2]), "r"(a[3]), "r"(b[0]), "r"(b[1]));
}
// pack (lo, hi) floats into bf16x2 (elem0 = lo in low 16 bits)
__device__ __forceinline__ uint32_t pack_bf16x2(float lo, float hi) {
    uint32_t r;
    asm("cvt.rn.bf16x2.f32 %0, %1, %2;" : "=r"(r) : "f"(hi), "f"(lo));
    return r;
}

// ---------------- kernel 0: weight prep ----------------
__global__ void __launch_bounds__(256) prep_kernel(
    const float* __restrict__ Wk, const float* __restrict__ Wv,
    const float* __restrict__ g,  const float* __restrict__ bb,
    const float* __restrict__ Wih, const float* __restrict__ Whh)
{
    const int tid = blockIdx.x * blockDim.x + threadIdx.x;
    const int nt  = gridDim.x * blockDim.x;
    const int lane = threadIdx.x & 31;
    const int gwarp = tid >> 5;

    for (int i = tid; i < EDIM * 128; i += nt) {
        int e = i >> 7, j = i & 127;
        float w  = (j < 64) ? Wk[e * 64 + j] : Wv[e * 64 + (j - 64)];
        float wp = g[e] * w;
        __nv_bfloat16 h = __float2bfloat16_rn(wp);
        g_Wh[i] = h;
        g_Wl[i] = __float2bfloat16_rn(wp - __bfloat162float(h));
    }

    if (gwarp < 128) {
        const int j = gwarp;
        float a = 0.f, c = 0.f;
        for (int e = lane; e < EDIM; e += 32) {
            float w = (j < 64) ? Wk[e * 64 + j] : Wv[e * 64 + (j - 64)];
            a += g[e] * w;
            c += bb[e] * w;
        }
#pragma unroll
        for (int off = 16; off; off >>= 1) {
            a += __shfl_xor_sync(0xffffffffu, a, off);
            c += __shfl_xor_sync(0xffffffffu, c, off);
        }
        if (lane == 0) { g_c1[j] = a; g_c2[j] = c; }
    }

    for (int i = tid; i < 192 * DDIM; i += nt) {
        int j = i / DDIM, d = i - j * DDIM;
        g_WihT[d * 192 + j] = Wih[i];
        g_WhhT[d * 192 + j] = Whh[i];
    }
}

// ---------------- kernel 1: fused LN + GEMM ----------------
struct SmemK1 {
    __nv_bfloat16 Ah[128][72];
    __nv_bfloat16 Al[128][72];
    __nv_bfloat16 Bh[64][136];
    __nv_bfloat16 Bl[64][136];
    float mean[128];
    float rstd[128];
};

__global__ void __launch_bounds__(256, 2) k1_kernel(const float* __restrict__ f)
{
    extern __shared__ char smraw[];
    SmemK1& sm = *reinterpret_cast<SmemK1*>(smraw);
    const int t    = threadIdx.x;
    const int lane = t & 31;
    const int warp = t >> 5;
    const int wm   = warp >> 2;
    const int wn   = warp & 3;
    const int m0   = blockIdx.x * 128;

    float s1[8], s2[8];
#pragma unroll
    for (int i = 0; i < 8; i++) { s1[i] = 0.f; s2[i] = 0.f; }
    float acc[4][4][4];
#pragma unroll
    for (int a = 0; a < 4; a++)
#pragma unroll
        for (int b = 0; b < 4; b++)
#pragma unroll
            for (int c = 0; c < 4; c++) acc[a][b][c] = 0.f;

    const int arsub = t >> 4;
    const int acol  = (t & 15) * 4;
    const int bcol  = (t & 15) * 8;

    for (int kk = 0; kk < 12; kk++) {
        const int kb = kk * 64;
#pragma unroll
        for (int i = 0; i < 8; i++) {
            int r = i * 16 + arsub;
            const float4 xv = *reinterpret_cast<const float4*>(
                f + (size_t)(m0 + r) * EDIM + kb + acol);
            s1[i] += xv.x + xv.y + xv.z + xv.w;
            s2[i] += xv.x * xv.x + xv.y * xv.y + xv.z * xv.z + xv.w * xv.w;
            // packed hi conversion
            uint32_t h01 = pack_bf16x2(xv.x, xv.y);
            uint32_t h23 = pack_bf16x2(xv.z, xv.w);
            // residuals via bit extraction (bf16 -> f32 is just a shift/mask)
            float r0 = xv.x - __uint_as_float(h01 << 16);
            float r1 = xv.y - __uint_as_float(h01 & 0xFFFF0000u);
            float r2 = xv.z - __uint_as_float(h23 << 16);
            float r3 = xv.w - __uint_as_float(h23 & 0xFFFF0000u);
            uint32_t l01 = pack_bf16x2(r0, r1);
            uint32_t l23 = pack_bf16x2(r2, r3);
            *reinterpret_cast<uint2*>(&sm.Ah[r][acol]) = make_uint2(h01, h23);
            *reinterpret_cast<uint2*>(&sm.Al[r][acol]) = make_uint2(l01, l23);
        }
#pragma unroll
        for (int i = 0; i < 4; i++) {
            int r = i * 16 + arsub;
            *reinterpret_cast<uint4*>(&sm.Bh[r][bcol]) =
                *reinterpret_cast<const uint4*>(&g_Wh[(kb + r) * 128 + bcol]);
            *reinterpret_cast<uint4*>(&sm.Bl[r][bcol]) =
                *reinterpret_cast<const uint4*>(&g_Wl[(kb + r) * 128 + bcol]);
        }
        __syncthreads();
#pragma unroll
        for (int ks = 0; ks < 4; ks++) {
            const int k0 = ks * 16;
            uint32_t bh[4][2], bl[4][2];
#pragma unroll
            for (int nt = 0; nt < 4; nt++) {
                const int n0 = wn * 32 + nt * 8;
                ldsm_x2t(bh[nt], &sm.Bh[k0 + (lane & 15)][n0]);
                ldsm_x2t(bl[nt], &sm.Bl[k0 + (lane & 15)][n0]);
            }
#pragma unroll
            for (int mt = 0; mt < 4; mt++) {
                uint32_t ah[4], al[4];
                const int ar = wm * 64 + mt * 16 + (lane & 15);
                const int ac = k0 + (lane >> 4) * 8;
                ldsm_x4(ah, &sm.Ah[ar][ac]);
                ldsm_x4(al, &sm.Al[ar][ac]);
#pragma unroll
                for (int nt = 0; nt < 4; nt++) {
                    mma16816(acc[mt][nt], ah, bh[nt]);
                    mma16816(acc[mt][nt], ah, bl[nt]);
                    mma16816(acc[mt][nt], al, bh[nt]);
                }
            }
        }
        __syncthreads();
    }

#pragma unroll
    for (int i = 0; i < 8; i++) {
        float a = s1[i], q = s2[i];
#pragma unroll
        for (int off = 8; off; off >>= 1) {
            a += __shfl_xor_sync(0xffffffffu, a, off);
            q += __shfl_xor_sync(0xffffffffu, q, off);
        }
        if ((t & 15) == 0) {
            int r = i * 16 + arsub;
            float mean = a * (1.0f / 768.0f);
            float var  = q * (1.0f / 768.0f) - mean * mean;
            sm.mean[r] = mean;
            sm.rstd[r] = rsqrtf(var + 1e-5f);
        }
    }
    __syncthreads();

#pragma unroll
    for (int mt = 0; mt < 4; mt++) {
#pragma unroll
        for (int nt = 0; nt < 4; nt++) {
            const int col = wn * 32 + nt * 8 + (lane & 3) * 2;
            const float c1a = g_c1[col],     c2a = g_c2[col];
            const float c1b = g_c1[col + 1], c2b = g_c2[col + 1];
#pragma unroll
            for (int hh = 0; hh < 2; hh++) {
                const int row = wm * 64 + mt * 16 + (lane >> 2) + hh * 8;
                const float rs = sm.rstd[row];
                const float base = -rs * sm.mean[row];
                float v0 = rs * acc[mt][nt][hh * 2 + 0] + base * c1a + c2a;
                float v1 = rs * acc[mt][nt][hh * 2 + 1] + base * c1b + c2b;
                *reinterpret_cast<float2*>(g_kv + (size_t)(m0 + row) * 128 + col)
                    = make_float2(v0, v1);
            }
        }
    }
}

// ---------------- kernel 2: slot attention + output ----------------
// v is NOT staged in smem: updates reads it from g_kv (L2-resident, warp-coalesced).
// This drops smem to ~90 KB -> 2 CTAs/SM.
struct SmemK2 {
    float ksm[NTOK][65];
    float attn[SLOTS][NTOK];
    float G1[SLOTS][192];
    float G2[SLOTS][192];
    float hbuf[SLOTS][HDIM];
    float slots[SLOTS][DDIM];
    float prev[SLOTS][DDIM];
    float qbuf[SLOTS][DDIM];
    float upd[SLOTS][DDIM];
    float lnb[SLOTS][DDIM];
    float rowinv[SLOTS];
};

__global__ void __launch_bounds__(K2_THREADS, 2) k2_kernel(
    const float* __restrict__ slots_init,
    const float* __restrict__ ln_s_g, const float* __restrict__ ln_s_b,
    const float* __restrict__ Wq,
    const float* __restrict__ b_ih, const float* __restrict__ b_hh,
    const float* __restrict__ ln_m_g, const float* __restrict__ ln_m_b,
    const float* __restrict__ W1, const float* __restrict__ b1,
    const float* __restrict__ W2, const float* __restrict__ b2,
    const float* __restrict__ Wo, const float* __restrict__ bo,
    float* __restrict__ out)
{
    extern __shared__ char smraw[];
    SmemK2& sm = *reinterpret_cast<SmemK2*>(smraw);
    const int t    = threadIdx.x;
    const int lane = t & 31;
    const int warp = t >> 5;
    const int b    = blockIdx.x;
    const float* kvbase = g_kv + (size_t)b * NTOK * 128;

    for (int idx = t; idx < NTOK * DDIM; idx += K2_THREADS) {
        int n = idx >> 6, d = idx & 63;
        sm.ksm[n][d] = kvbase[n * 128 + d];
    }
    for (int idx = t; idx < SLOTS * DDIM; idx += K2_THREADS)
        sm.slots[idx >> 6][idx & 63] = slots_init[idx];
    __syncthreads();

    for (int it = 0; it < 3; it++) {
        for (int idx = t; idx < SLOTS * DDIM; idx += K2_THREADS)
            sm.prev[idx >> 6][idx & 63] = sm.slots[idx >> 6][idx & 63];
        __syncthreads();
        // LN(slots; ln_s)
        for (int s = warp; s < SLOTS; s += K2_WARPS) {
            float x0 = sm.slots[s][lane], x1 = sm.slots[s][lane + 32];
            float su = x0 + x1, sq = x0 * x0 + x1 * x1;
#pragma unroll
            for (int off = 16; off; off >>= 1) {
                su += __shfl_xor_sync(0xffffffffu, su, off);
                sq += __shfl_xor_sync(0xffffffffu, sq, off);
            }
            float mean = su * (1.f / 64.f);
            float rs   = rsqrtf(sq * (1.f / 64.f) - mean * mean + 1e-5f);
            sm.lnb[s][lane]      = (x0 - mean) * rs * __ldg(ln_s_g + lane)      + __ldg(ln_s_b + lane);
            sm.lnb[s][lane + 32] = (x1 - mean) * rs * __ldg(ln_s_g + lane + 32) + __ldg(ln_s_b + lane + 32);
        }
        __syncthreads();
        // q = lnb @ Wq  (2-way accum split)
        for (int idx = t; idx < SLOTS * DDIM; idx += K2_THREADS) {
            int s = idx >> 6, d = idx & 63;
            float a0 = 0.f, a1 = 0.f;
#pragma unroll
            for (int e = 0; e < 64; e += 2) {
                a0 += sm.lnb[s][e]     * __ldg(Wq + e * 64 + d);
                a1 += sm.lnb[s][e + 1] * __ldg(Wq + (e + 1) * 64 + d);
            }
            sm.qbuf[s][d] = a0 + a1;
        }
        __syncthreads();
        // dots = scale * q @ k^T  (4-way accum split)
        for (int idx = t; idx < SLOTS * NTOK; idx += K2_THREADS) {
            int s = idx / NTOK, n = idx - s * NTOK;
            float a0 = 0.f, a1 = 0.f, a2 = 0.f, a3 = 0.f;
#pragma unroll
            for (int c = 0; c < 64; c += 4) {
                a0 += sm.qbuf[s][c]     * sm.ksm[n][c];
                a1 += sm.qbuf[s][c + 1] * sm.ksm[n][c + 1];
                a2 += sm.qbuf[s][c + 2] * sm.ksm[n][c + 2];
                a3 += sm.qbuf[s][c + 3] * sm.ksm[n][c + 3];
            }
            sm.attn[s][n] = 0.125f * ((a0 + a1) + (a2 + a3));
        }
        __syncthreads();
        // softmax over slots + EPS
        for (int n = t; n < NTOK; n += K2_THREADS) {
            float mx = -1e30f;
#pragma unroll
            for (int s = 0; s < SLOTS; s++) mx = fmaxf(mx, sm.attn[s][n]);
            float e_[SLOTS]; float sum = 0.f;
#pragma unroll
            for (int s = 0; s < SLOTS; s++) { e_[s] = __expf(sm.attn[s][n] - mx); sum += e_[s]; }
            float inv = 1.f / sum;
#pragma unroll
            for (int s = 0; s < SLOTS; s++) sm.attn[s][n] = e_[s] * inv + 1e-8f;
        }
        __syncthreads();
        // row sums (renorm over inputs)
        for (int s = warp; s < SLOTS; s += K2_WARPS) {
            float a = 0.f;
            for (int n = lane; n < NTOK; n += 32) a += sm.attn[s][n];
#pragma unroll
            for (int off = 16; off; off >>= 1) a += __shfl_xor_sync(0xffffffffu, a, off);
            if (lane == 0) sm.rowinv[s] = 1.f / a;
        }
        __syncthreads();
        // updates = (attn/rowsum) @ v   — v streamed from g_kv, 4-way accum
        for (int idx = t; idx < SLOTS * DDIM; idx += K2_THREADS) {
            int s = idx >> 6, d = idx & 63;
            const float* vg = kvbase + 64 + d;
            float a0 = 0.f, a1 = 0.f, a2 = 0.f, a3 = 0.f;
            int n = 0;
#pragma unroll 4
            for (; n + 4 <= NTOK; n += 4) {
                a0 += sm.attn[s][n]     * __ldg(vg + (n)     * 128);
                a1 += sm.attn[s][n + 1] * __ldg(vg + (n + 1) * 128);
                a2 += sm.attn[s][n + 2] * __ldg(vg + (n + 2) * 128);
                a3 += sm.attn[s][n + 3] * __ldg(vg + (n + 3) * 128);
            }
            for (; n < NTOK; n++) a0 += sm.attn[s][n] * __ldg(vg + n * 128);
            sm.upd[s][d] = ((a0 + a1) + (a2 + a3)) * sm.rowinv[s];
        }
        __syncthreads();
        // GRU gate pre-activations (2x2 accum split)
        for (int idx = t; idx < SLOTS * 192; idx += K2_THREADS) {
            int s = idx / 192, j = idx - s * 192;
            float a0 = __ldg(b_ih + j), a1 = 0.f;
            float c0 = __ldg(b_hh + j), c1 = 0.f;
#pragma unroll
            for (int d = 0; d < 64; d += 2) {
                a0 += sm.upd[s][d]      * g_WihT[d * 192 + j];
                a1 += sm.upd[s][d + 1]  * g_WihT[(d + 1) * 192 + j];
                c0 += sm.prev[s][d]     * g_WhhT[d * 192 + j];
                c1 += sm.prev[s][d + 1] * g_WhhT[(d + 1) * 192 + j];
            }
            sm.G1[s][j] = a0 + a1; sm.G2[s][j] = c0 + c1;
        }
        __syncthreads();
        // gates + state update
        for (int idx = t; idx < SLOTS * DDIM; idx += K2_THREADS) {
            int s = idx >> 6, d = idx & 63;
            float r  = 1.f / (1.f + __expf(-(sm.G1[s][d]      + sm.G2[s][d])));
            float z  = 1.f / (1.f + __expf(-(sm.G1[s][64 + d] + sm.G2[s][64 + d])));
            float nn = tanhf(sm.G1[s][128 + d] + r * sm.G2[s][128 + d]);
            sm.slots[s][d] = (1.f - z) * nn + z * sm.prev[s][d];
        }
        __syncthreads();
        // LN(slots; ln_m)
        for (int s = warp; s < SLOTS; s += K2_WARPS) {
            float x0 = sm.slots[s][lane], x1 = sm.slots[s][lane + 32];
            float su = x0 + x1, sq = x0 * x0 + x1 * x1;
#pragma unroll
            for (int off = 16; off; off >>= 1) {
                su += __shfl_xor_sync(0xffffffffu, su, off);
                sq += __shfl_xor_sync(0xffffffffu, sq, off);
            }
            float mean = su * (1.f / 64.f);
            float rs   = rsqrtf(sq * (1.f / 64.f) - mean * mean + 1e-5f);
            sm.lnb[s][lane]      = (x0 - mean) * rs * __ldg(ln_m_g + lane)      + __ldg(ln_m_b + lane);
            sm.lnb[s][lane + 32] = (x1 - mean) * rs * __ldg(ln_m_g + lane + 32) + __ldg(ln_m_b + lane + 32);
        }
        __syncthreads();
        // h = relu(lnb @ W1 + b1)  (2-way)
        for (int idx = t; idx < SLOTS * HDIM; idx += K2_THREADS) {
            int s = idx >> 7, i = idx & 127;
            float a0 = __ldg(b1 + i), a1 = 0.f;
#pragma unroll
            for (int d = 0; d < 64; d += 2) {
                a0 += sm.lnb[s][d]     * __ldg(W1 + d * 128 + i);
                a1 += sm.lnb[s][d + 1] * __ldg(W1 + (d + 1) * 128 + i);
            }
            sm.hbuf[s][i] = fmaxf(a0 + a1, 0.f);
        }
        __syncthreads();
        // slots += h @ W2 + b2  (2-way)
        for (int idx = t; idx < SLOTS * DDIM; idx += K2_THREADS) {
            int s = idx >> 6, d = idx & 63;
            float a0 = __ldg(b2 + d), a1 = 0.f;
#pragma unroll
            for (int i = 0; i < 128; i += 2) {
                a0 += sm.hbuf[s][i]     * __ldg(W2 + i * 64 + d);
                a1 += sm.hbuf[s][i + 1] * __ldg(W2 + (i + 1) * 64 + d);
            }
            sm.slots[s][d] += a0 + a1;
        }
        __syncthreads();
    }

    float* out2 = out + OUT_ELEMS;
    for (int idx = t; idx < SLOTS * DDIM; idx += K2_THREADS)
        out2[(size_t)b * SLOTS * DDIM + idx] = sm.slots[idx >> 6][idx & 63];

    for (int o = t; o < ODIM; o += K2_THREADS) {
        float a[SLOTS];
        const float bov = __ldg(bo + o);
#pragma unroll
        for (int s = 0; s < SLOTS; s++) a[s] = bov;
        for (int d = 0; d < 64; d++) {
            const float w = __ldg(Wo + d * ODIM + o);
            const float* sl = &sm.slots[0][0];
#pragma unroll
            for (int s = 0; s < SLOTS; s++) a[s] += sl[s * DDIM + d] * w;
        }
#pragma unroll
        for (int s = 0; s < SLOTS; s++)
            out[((size_t)(b * SLOTS + s)) * ODIM + o] = fmaxf(a[s], 0.f);
    }
}

// ---------------- launch ----------------
extern "C" void kernel_launch(void* const* d_in, const int* in_sizes, int n_in,
                              void* d_out, int out_size)
{
    const float* features   = (const float*)d_in[0];
    const float* ln_in_g    = (const float*)d_in[1];
    const float* ln_in_b    = (const float*)d_in[2];
    const float* slots_init = (const float*)d_in[3];
    const float* ln_s_g     = (const float*)d_in[4];
    const float* ln_s_b     = (const float*)d_in[5];
    const float* Wq         = (const float*)d_in[6];
    const float* Wk         = (const float*)d_in[7];
    const float* Wv         = (const float*)d_in[8];
    const float* W_ih       = (const float*)d_in[9];
    const float* W_hh       = (const float*)d_in[10];
    const float* b_ih       = (const float*)d_in[11];
    const float* b_hh       = (const float*)d_in[12];
    const float* ln_m_g     = (const float*)d_in[13];
    const float* ln_m_b     = (const float*)d_in[14];
    const float* W1         = (const float*)d_in[15];
    const float* b1         = (const float*)d_in[16];
    const float* W2         = (const float*)d_in[17];
    const float* b2         = (const float*)d_in[18];
    const float* Wo         = (const float*)d_in[19];
    const float* bo         = (const float*)d_in[20];
    float* out = (float*)d_out;

    cudaFuncSetAttribute(k1_kernel, cudaFuncAttributeMaxDynamicSharedMemorySize,
                         (int)sizeof(SmemK1));
    cudaFuncSetAttribute(k2_kernel, cudaFuncAttributeMaxDynamicSharedMemorySize,
                         (int)sizeof(SmemK2));

    prep_kernel<<<256, 256>>>(Wk, Wv, ln_in_g, ln_in_b, W_ih, W_hh);
    k1_kernel<<<MROWS / 128, 256, sizeof(SmemK1)>>>(features);
    k2_kernel<<<BATCH, K2_THREADS, sizeof(SmemK2)>>>(slots_init, ln_s_g, ln_s_b, Wq,
                                                     b_ih, b_hh, ln_m_g, ln_m_b,
                                                     W1, b1, W2, b2, Wo, bo, out);
}